// round 14
// baseline (speedup 1.0000x reference)
#include <cuda_runtime.h>
#include <cstddef>
#include <math.h>
#include <stdint.h>

#define B_ 32
#define T_ 512
#define D_ 1024
#define U_ 1024
#define BBU_ 2048
#define NBLK 128
#define NTHR 512
#define RING 4
#define NCHUNK (T_ * 20)

typedef unsigned long long ull;

// ---------------- persistent scratch (device globals; no runtime alloc) ----------------
__device__ float g_xn[B_*T_*D_];        // layernormed x
__device__ float g_cfcx[B_*T_*D_];      // xn @ w_in + b_in           [b][t][d]
__device__ float g_P0[B_*T_*BBU_];      // cfc_x @ W0[:1024]          [b*t][c]
__device__ float g_P0T[T_*BBU_*B_];     // transposed                 [t][c][b]
__device__ float g_cfco[B_*T_*U_];      // scan outputs               [b][t][u]
__device__ float g_h[U_*B_];            // hidden, pair layout [u/2][b][2]
__device__ float g_bb0[BBU_*B_];        // bb l0 out, pair layout [c/2][b][2]
__device__ float g_bb1[BBU_*B_];        // bb l1 out, pair layout
__device__ float g_pkA[NBLK*1024*16];   // packed W0h per-CTA slices (8MB)
__device__ float g_pkH[NBLK*2048*32];   // packed head weights per-CTA (32MB)
__device__ float g_zero[BBU_];          // zero bias
__device__ __align__(16) unsigned g_barA[16];  // hierarchical barrier counters

// ---------------- helpers ----------------
__device__ __forceinline__ unsigned sptr(const void* p){
  return (unsigned)__cvta_generic_to_shared(p);
}

// hierarchical grid barrier: 16 counters, 8 CTAs each; target = nbar*8 per counter
__device__ __forceinline__ void grid_bar(int cta, unsigned target){
  __syncthreads();
  if (threadIdx.x == 0){
    __threadfence();                       // release our stage writes
    atomicAdd(&g_barA[cta & 15], 1u);
    while (true){
      bool ok = true;
      #pragma unroll
      for (int i = 0; i < 4; i++){
        uint4 v;
        asm volatile("ld.volatile.global.v4.u32 {%0,%1,%2,%3}, [%4];"
                     : "=r"(v.x), "=r"(v.y), "=r"(v.z), "=r"(v.w)
                     : "l"(g_barA + i * 4));
        ok &= (v.x >= target) & (v.y >= target) & (v.z >= target) & (v.w >= target);
      }
      if (ok) break;
      __nanosleep(16);
    }
    __threadfence();                       // acquire: gpu fence invalidates L1D
  }
  __syncthreads();
}

__device__ __forceinline__ ull fma2(ull x, ull y, ull z){
  ull d;
  asm("fma.rn.f32x2 %0, %1, %2, %3;" : "=l"(d) : "l"(x), "l"(y), "l"(z));
  return d;
}
__device__ __forceinline__ ull pack2(float a){
  unsigned au = __float_as_uint(a);
  ull p;
  asm("mov.b64 %0, {%1, %1};" : "=l"(p) : "r"(au));
  return p;
}
__device__ __forceinline__ void unpack2(ull v, float& lo, float& hi){
  unsigned l, h;
  asm("mov.b64 {%0, %1}, %2;" : "=r"(l), "=r"(h) : "l"(v));
  lo = __uint_as_float(l); hi = __uint_as_float(h);
}
#define LL(x) __double_as_longlong(x)

// mbarrier ops
__device__ __forceinline__ void mbar_init(unsigned mb, unsigned cnt){
  asm volatile("mbarrier.init.shared.b64 [%0], %1;" :: "r"(mb), "r"(cnt) : "memory");
}
__device__ __forceinline__ void mbar_arrive(unsigned mb){
  asm volatile("mbarrier.arrive.shared.b64 _, [%0];" :: "r"(mb) : "memory");
}
__device__ __forceinline__ void tma_issue(unsigned mb, unsigned dst, const float* src){
  asm volatile("mbarrier.arrive.expect_tx.shared.b64 _, [%0], %1;"
               :: "r"(mb), "r"(16384u) : "memory");
  asm volatile("cp.async.bulk.shared::cta.global.mbarrier::complete_tx::bytes "
               "[%0], [%1], %2, [%3];"
               :: "r"(dst), "l"(src), "r"(16384u), "r"(mb) : "memory");
}
__device__ __forceinline__ void mbar_wait(unsigned mb, unsigned ph){
  unsigned done;
  do {
    asm volatile(
      "{\n\t.reg .pred p;\n\t"
      "mbarrier.try_wait.parity.shared::cta.b64 p, [%1], %2, 0x989680;\n\t"
      "selp.b32 %0, 1, 0, p;\n\t}"
      : "=r"(done) : "r"(mb), "r"(ph) : "memory");
  } while (!done);
}

// 16KB chunks: per step 4 chunks of pkA (bb0-h) + 16 chunks of pkH (head)
__device__ __forceinline__ const float* chunk_src(int cta, int chunk){
  int p = chunk % 20;
  return (p < 4) ? g_pkA + (((size_t)cta) << 14) + ((size_t)p << 12)
                 : g_pkH + (((size_t)cta) << 16) + ((size_t)(p - 4) << 12);
}

// ---------------- LayerNorm ----------------
__global__ void k_ln(const float* __restrict__ x, const float* __restrict__ gw,
                     const float* __restrict__ gb){
  int row = blockIdx.x;
  int tid = threadIdx.x;
  const float4* xr = (const float4*)(x + (size_t)row * D_);
  float4 v = xr[tid];
  float s = v.x + v.y + v.z + v.w;
  float q = v.x*v.x + v.y*v.y + v.z*v.z + v.w*v.w;
  #pragma unroll
  for (int o = 16; o > 0; o >>= 1){
    s += __shfl_xor_sync(0xffffffffu, s, o);
    q += __shfl_xor_sync(0xffffffffu, q, o);
  }
  __shared__ float ss[8], sq[8];
  if ((tid & 31) == 0){ ss[tid >> 5] = s; sq[tid >> 5] = q; }
  __syncthreads();
  if (tid == 0){
    float a = 0.f, c = 0.f;
    #pragma unroll
    for (int i = 0; i < 8; i++){ a += ss[i]; c += sq[i]; }
    ss[0] = a; sq[0] = c;
  }
  __syncthreads();
  float mu  = ss[0] * (1.0f / D_);
  float var = sq[0] * (1.0f / D_) - mu * mu;
  float r   = rsqrtf(var + 1e-5f);
  float4 wv = ((const float4*)gw)[tid];
  float4 bv = ((const float4*)gb)[tid];
  float4 o;
  o.x = (v.x - mu) * r * wv.x + bv.x;
  o.y = (v.y - mu) * r * wv.y + bv.y;
  o.z = (v.z - mu) * r * wv.z + bv.z;
  o.w = (v.w - mu) * r * wv.w + bv.w;
  ((float4*)(g_xn + (size_t)row * D_))[tid] = o;
}

// ---------------- double-buffered fp32 SGEMM: C = A[M,K]@W[K,N] + bias (+res) ----------------
// tiles: 64(M) x 128(N), 256 threads, 16-deep k-slabs
__global__ void __launch_bounds__(256) k_gemm(
    const float* __restrict__ A, const float* __restrict__ W,
    const float* __restrict__ bias, const float* __restrict__ res,
    float* __restrict__ C, int M, int N, int K)
{
  __shared__ float As[2][16][64];
  __shared__ float Ws[2][16][128];
  int tid = threadIdx.x;
  int bn = blockIdx.x * 128, bm = blockIdx.y * 64;
  int tx = tid & 15, ty = tid >> 4;
  int lam = tid >> 2, lak = (tid & 3) * 4;
  int lwk = tid >> 4, lwn = (tid & 15) * 8;
  float acc[4][8] = {};

  const float* Arow = A + (size_t)(bm + lam) * K + lak;
  const float* Wrow = W + (size_t)lwk * N + bn + lwn;

  {
    float4 av  = *(const float4*)(Arow);
    float4 wv0 = *(const float4*)(Wrow);
    float4 wv1 = *(const float4*)(Wrow + 4);
    As[0][lak+0][lam] = av.x; As[0][lak+1][lam] = av.y;
    As[0][lak+2][lam] = av.z; As[0][lak+3][lam] = av.w;
    *(float4*)&Ws[0][lwk][lwn]     = wv0;
    *(float4*)&Ws[0][lwk][lwn + 4] = wv1;
  }
  __syncthreads();

  int buf = 0;
  for (int k0 = 16; k0 <= K; k0 += 16){
    float4 nav, nwv0, nwv1;
    if (k0 < K){
      nav  = *(const float4*)(Arow + k0);
      nwv0 = *(const float4*)(Wrow + (size_t)k0 * N);
      nwv1 = *(const float4*)(Wrow + (size_t)k0 * N + 4);
    }
    #pragma unroll
    for (int k = 0; k < 16; k++){
      float4 a4 = *(float4*)&As[buf][k][ty * 4];
      float4 b0 = *(float4*)&Ws[buf][k][tx * 8];
      float4 b1 = *(float4*)&Ws[buf][k][tx * 8 + 4];
      float a_[4]; *(float4*)a_ = a4;
      float b_[8]; *(float4*)b_ = b0; *(float4*)(b_ + 4) = b1;
      #pragma unroll
      for (int i = 0; i < 4; i++)
        #pragma unroll
        for (int j = 0; j < 8; j++)
          acc[i][j] = fmaf(a_[i], b_[j], acc[i][j]);
    }
    if (k0 < K){
      buf ^= 1;
      As[buf][lak+0][lam] = nav.x; As[buf][lak+1][lam] = nav.y;
      As[buf][lak+2][lam] = nav.z; As[buf][lak+3][lam] = nav.w;
      *(float4*)&Ws[buf][lwk][lwn]     = nwv0;
      *(float4*)&Ws[buf][lwk][lwn + 4] = nwv1;
      __syncthreads();
    }
  }

  float4 bv0 = *(const float4*)(bias + bn + tx * 8);
  float4 bv1 = *(const float4*)(bias + bn + tx * 8 + 4);
  #pragma unroll
  for (int i = 0; i < 4; i++){
    size_t m = (size_t)bm + ty * 4 + i;
    float4 o0 = make_float4(acc[i][0] + bv0.x, acc[i][1] + bv0.y,
                            acc[i][2] + bv0.z, acc[i][3] + bv0.w);
    float4 o1 = make_float4(acc[i][4] + bv1.x, acc[i][5] + bv1.y,
                            acc[i][6] + bv1.z, acc[i][7] + bv1.w);
    if (res){
      float4 r0 = *(const float4*)(res + m * N + bn + tx * 8);
      float4 r1 = *(const float4*)(res + m * N + bn + tx * 8 + 4);
      o0.x += r0.x; o0.y += r0.y; o0.z += r0.z; o0.w += r0.w;
      o1.x += r1.x; o1.y += r1.y; o1.z += r1.z; o1.w += r1.w;
    }
    *(float4*)(C + m * N + bn + tx * 8)     = o0;
    *(float4*)(C + m * N + bn + tx * 8 + 4) = o1;
  }
}

// ---------------- transpose P0 [b][t][2048] -> [t][c][b] ----------------
__global__ void k_transP0(){
  __shared__ float tile[32][33];
  int c0 = blockIdx.x * 32, t = blockIdx.y;
  int lane = threadIdx.x & 31, r = threadIdx.x >> 5;
  #pragma unroll
  for (int i = 0; i < 4; i++){
    int b = r * 4 + i;
    tile[b][lane] = g_P0[((size_t)b * T_ + t) * BBU_ + c0 + lane];
  }
  __syncthreads();
  #pragma unroll
  for (int i = 0; i < 4; i++){
    int c = r * 4 + i;
    g_P0T[((size_t)t * BBU_ + c0 + c) * 32 + lane] = tile[lane][c];
  }
}

// ---------------- init hidden (pair layout) ----------------
__global__ void k_initT(const float* __restrict__ hid){
  int i = blockIdx.x * 256 + threadIdx.x;   // 32768
  int u = i >> 5, b = i & 31;
  g_h[((u >> 1) << 6) + b * 2 + (u & 1)] = hid[(size_t)b * U_ + u];
}

// ---------------- pack streamed weights into per-CTA contiguous slices ----------------
#define NP4A (NBLK * 1024 * 4)
#define NP4H (NBLK * 2048 * 8)
__global__ void k_pack(const float* __restrict__ W0,
                       const float* __restrict__ wff1, const float* __restrict__ wff2,
                       const float* __restrict__ wta,  const float* __restrict__ wtb){
  int q = blockIdx.x * 256 + threadIdx.x;
  if (q < NP4A){
    int cta = q >> 12, rem = q & 4095;
    int k = rem >> 2, c4 = (rem & 3) << 2;
    *(float4*)&g_pkA[(((size_t)cta << 10) + k) * 16 + c4] =
        *(const float4*)&W0[(size_t)(1024 + k) * BBU_ + cta * 16 + c4];
  } else if (q < NP4A + NP4H){
    int q2 = q - NP4A;
    int cta = q2 >> 14, rem = q2 & 16383;
    int k = rem >> 3, g8 = rem & 7;
    int m = g8 >> 1, h4 = (g8 & 1) << 2;
    const float* wm = (m == 0) ? wff1 : (m == 1) ? wff2 : (m == 2) ? wta : wtb;
    *(float4*)&g_pkH[(((size_t)cta << 11) + k) * 32 + m * 8 + h4] =
        *(const float4*)&wm[(size_t)k * U_ + cta * 8 + h4];
  }
}

// ---------------- persistent scan kernel ----------------
// SMEM: sW1 131072 | ring 4x16384 | red 33792 | mbars full[4]+empty[4]
#define SM_W1   0
#define SM_RING 131072
#define SM_RED  (131072 + RING * 16384)
#define SM_MBAR (SM_RED + 33792)
#define SM_TOTAL (SM_MBAR + 64)

__global__ void __launch_bounds__(NTHR, 1) k_scan(
    const float* __restrict__ tsp,
    const float* __restrict__ bbw,  const float* __restrict__ bbb,
    const float* __restrict__ bff1, const float* __restrict__ bff2,
    const float* __restrict__ bta,  const float* __restrict__ btb,
    float* __restrict__ hf)
{
  extern __shared__ char smem[];
  float* sW1   = (float*)(smem + SM_W1);
  float* ringf = (float*)(smem + SM_RING);
  float* red   = (float*)(smem + SM_RED);
  unsigned fullb[RING], emptyb[RING], ringu[RING];
  #pragma unroll
  for (int s = 0; s < RING; s++){
    fullb[s]  = sptr(smem + SM_MBAR + s * 8);
    emptyb[s] = sptr(smem + SM_MBAR + 32 + s * 8);
    ringu[s]  = sptr(smem + SM_RING + s * 16384);
  }

  int tid = threadIdx.x, cta = blockIdx.x;
  int lane = tid & 31, w = tid >> 5;    // 16 warps
  unsigned nbar = 0;
  const float* W1 = bbw + (size_t)BBU_ * BBU_;
  const float* b1 = bbb + BBU_;

  if (tid == 0){
    #pragma unroll
    for (int s = 0; s < RING; s++){ mbar_init(fullb[s], 1); mbar_init(emptyb[s], 16); }
  }
  // load persistent W1 slice: sW1[k][16]
  for (int i = tid; i < 2048 * 4; i += NTHR){
    int k = i >> 2, c4 = (i & 3) << 2;
    *(float4*)&sW1[k * 16 + c4] = *(const float4*)&W1[(size_t)k * BBU_ + cta * 16 + c4];
  }
  __syncthreads();

  if (tid == 0){
    #pragma unroll
    for (int s = 0; s < RING; s++) tma_issue(fullb[s], ringu[s], chunk_src(cta, s));
  }

  // per-thread P0T index (used in bb0 reduction): cc = cta*16 + (tid>>5), b2 = tid&31
  const float* p0_addr = g_P0T + ((size_t)(cta * 16 + (tid >> 5))) * 32 + (tid & 31);

  int it = 0;
  for (int t = 0; t < T_; t++){
    // prefetch P0T term for this step early (DRAM-resident; hide behind chunk loop)
    float p0v = p0_addr[(size_t)t * BBU_ * 32];

    // ======= bb layer 0: 16 cols/warp (acc[8]), 16-way k-split; h-half streamed =======
    {
      ull acc[8] = {0ull,0ull,0ull,0ull,0ull,0ull,0ull,0ull};
      #pragma unroll
      for (int c = 0; c < 4; c++){
        int slot = it % RING; unsigned par = (unsigned)(it / RING) & 1u;
        mbar_wait(fullb[slot], par);
        const float* wb = ringf + slot * 4096 + (w * 16) * 16;   // 16 local k-rows x 16 cols
        const float* ap = g_h + (size_t)((c * 256 + w * 16) >> 1) * 64 + lane * 2;
        #pragma unroll
        for (int kk = 0; kk < 8; kk++){
          float2 av = *(const float2*)(ap + kk * 64);
          ull a0 = pack2(av.x), a1 = pack2(av.y);
          const double2* e = (const double2*)(wb + kk * 32);       // even k row
          const double2* o = (const double2*)(wb + kk * 32 + 16);  // odd k row
          #pragma unroll
          for (int j = 0; j < 4; j++){
            double2 we = e[j], wo = o[j];
            acc[2*j]   = fma2(a0, LL(we.x), acc[2*j]);
            acc[2*j+1] = fma2(a0, LL(we.y), acc[2*j+1]);
            acc[2*j]   = fma2(a1, LL(wo.x), acc[2*j]);
            acc[2*j+1] = fma2(a1, LL(wo.y), acc[2*j+1]);
          }
        }
        if (lane == 0) mbar_arrive(emptyb[slot]);
        if (tid == 0 && it + RING < NCHUNK){
          mbar_wait(emptyb[slot], par);
          tma_issue(fullb[slot], ringu[slot], chunk_src(cta, it + RING));
        }
        it++;
      }
      #pragma unroll
      for (int i = 0; i < 8; i++){
        float lo, hi; unpack2(acc[i], lo, hi);
        red[(w * 16 + 2*i    ) * 33 + lane] = lo;
        red[(w * 16 + 2*i + 1) * 33 + lane] = hi;
      }
      __syncthreads();
      int b2 = tid & 31, cl = tid >> 5;
      float s = 0.f;
      #pragma unroll
      for (int k2 = 0; k2 < 16; k2++) s += red[(k2 * 16 + cl) * 33 + b2];
      int cc = cta * 16 + cl;
      s += p0v + bbb[cc];
      g_bb0[((size_t)(cc >> 1)) * 64 + b2 * 2 + (cc & 1)] = 1.7159f * tanhf(0.666f * s);
    }
    grid_bar(cta, ++nbar * 8);

    // ======= bb layer 1: 16 cols/warp, 16-way k-split; weights persistent in SMEM =======
    {
      ull acc[8] = {0ull,0ull,0ull,0ull,0ull,0ull,0ull,0ull};
      const float* wb = sW1 + (w * 128) * 16;
      const float* ap = g_bb0 + (size_t)((w * 128) >> 1) * 64 + lane * 2;
      #pragma unroll 8
      for (int kk = 0; kk < 64; kk++){
        float2 av = *(const float2*)(ap + kk * 64);
        ull a0 = pack2(av.x), a1 = pack2(av.y);
        const double2* e = (const double2*)(wb + kk * 32);
        const double2* o = (const double2*)(wb + kk * 32 + 16);
        #pragma unroll
        for (int j = 0; j < 4; j++){
          double2 we = e[j], wo = o[j];
          acc[2*j]   = fma2(a0, LL(we.x), acc[2*j]);
          acc[2*j+1] = fma2(a0, LL(we.y), acc[2*j+1]);
          acc[2*j]   = fma2(a1, LL(wo.x), acc[2*j]);
          acc[2*j+1] = fma2(a1, LL(wo.y), acc[2*j+1]);
        }
      }
      #pragma unroll
      for (int i = 0; i < 8; i++){
        float lo, hi; unpack2(acc[i], lo, hi);
        red[(w * 16 + 2*i    ) * 33 + lane] = lo;
        red[(w * 16 + 2*i + 1) * 33 + lane] = hi;
      }
      __syncthreads();
      int b2 = tid & 31, cl = tid >> 5;
      float s = 0.f;
      #pragma unroll
      for (int k2 = 0; k2 < 16; k2++) s += red[(k2 * 16 + cl) * 33 + b2];
      int cc = cta * 16 + cl;
      s += b1[cc];
      g_bb1[((size_t)(cc >> 1)) * 64 + b2 * 2 + (cc & 1)] = 1.7159f * tanhf(0.666f * s);
    }
    grid_bar(cta, ++nbar * 8);

    // ======= head: 16 cols/warp (2 col-groups x 8 k-split); weights streamed =======
    {
      ull acc[8] = {0ull,0ull,0ull,0ull,0ull,0ull,0ull,0ull};
      int g = w & 1, ks = w >> 1;
      for (int c = 0; c < 16; c++){
        int slot = it % RING; unsigned par = (unsigned)(it / RING) & 1u;
        mbar_wait(fullb[slot], par);
        const float* wb = ringf + slot * 4096 + (ks * 16) * 32 + g * 16;
        const float* ap = g_bb1 + (size_t)((c * 128 + ks * 16) >> 1) * 64 + lane * 2;
        #pragma unroll
        for (int kk = 0; kk < 8; kk++){
          float2 av = *(const float2*)(ap + kk * 64);
          ull a0 = pack2(av.x), a1 = pack2(av.y);
          const double2* e = (const double2*)(wb + kk * 64);
          const double2* o = (const double2*)(wb + kk * 64 + 32);
          #pragma unroll
          for (int j = 0; j < 4; j++){
            double2 we = e[j], wo = o[j];
            acc[2*j]   = fma2(a0, LL(we.x), acc[2*j]);
            acc[2*j+1] = fma2(a0, LL(we.y), acc[2*j+1]);
            acc[2*j]   = fma2(a1, LL(wo.x), acc[2*j]);
            acc[2*j+1] = fma2(a1, LL(wo.y), acc[2*j+1]);
          }
        }
        if (lane == 0) mbar_arrive(emptyb[slot]);
        if (tid == 0 && it + RING < NCHUNK){
          mbar_wait(emptyb[slot], par);
          tma_issue(fullb[slot], ringu[slot], chunk_src(cta, it + RING));
        }
        it++;
      }
      #pragma unroll
      for (int i = 0; i < 8; i++){
        float lo, hi; unpack2(acc[i], lo, hi);
        red[(ks * 32 + g * 16 + 2*i    ) * 33 + lane] = lo;
        red[(ks * 32 + g * 16 + 2*i + 1) * 33 + lane] = hi;
      }
      __syncthreads();
      if (tid < 256){
        int b2 = tid >> 3, uu = tid & 7;
        float s0 = 0.f, s1 = 0.f, s2 = 0.f, s3 = 0.f;
        #pragma unroll
        for (int k2 = 0; k2 < 8; k2++){
          s0 += red[(k2 * 32 +  0 + uu) * 33 + b2];
          s1 += red[(k2 * 32 +  8 + uu) * 33 + b2];
          s2 += red[(k2 * 32 + 16 + uu) * 33 + b2];
          s3 += red[(k2 * 32 + 24 + uu) * 33 + b2];
        }
        int u = cta * 8 + uu;
        float f1  = tanhf(s0 + bff1[u]);
        float f2  = tanhf(s1 + bff2[u]);
        float tav = s2 + bta[u], tbv = s3 + btb[u];
        float ts  = tsp[(size_t)b2 * T_ + t];
        float sig = 1.f / (1.f + expf(-(tav * ts + tbv)));
        float hn  = f1 * (1.f - sig) + sig * f2;
        g_h[((size_t)(u >> 1)) * 64 + b2 * 2 + (u & 1)] = hn;
        g_cfco[((size_t)b2 * T_ + t) * U_ + u] = hn;
      }
    }
    grid_bar(cta, ++nbar * 8);
  }

  if (hf){
    for (int i = cta * NTHR + tid; i < B_ * U_; i += NBLK * NTHR){
      int b = i >> 10, u = i & 1023;
      hf[i] = g_h[((size_t)(u >> 1)) * 64 + b * 2 + (u & 1)];
    }
  }
}

// ---------------- launch ----------------
extern "C" void kernel_launch(void* const* d_in, const int* in_sizes, int n_in,
                              void* d_out, int out_size){
  (void)in_sizes; (void)n_in;
  const float* x    = (const float*)d_in[0];
  const float* tsp  = (const float*)d_in[1];
  const float* hid  = (const float*)d_in[2];
  const float* nw   = (const float*)d_in[3];
  const float* nb   = (const float*)d_in[4];
  const float* w_in = (const float*)d_in[5];
  const float* b_in = (const float*)d_in[6];
  const float* bbw  = (const float*)d_in[7];
  const float* bbb  = (const float*)d_in[8];
  const float* wff1 = (const float*)d_in[9];
  const float* bff1 = (const float*)d_in[10];
  const float* wff2 = (const float*)d_in[11];
  const float* bff2 = (const float*)d_in[12];
  const float* wta  = (const float*)d_in[13];
  const float* bta  = (const float*)d_in[14];
  const float* wtb  = (const float*)d_in[15];
  const float* btb  = (const float*)d_in[16];
  const float* wout = (const float*)d_in[17];
  const float* bout = (const float*)d_in[18];
  float* out = (float*)d_out;

  static int smem_set = 0;
  if (!smem_set){
    cudaFuncSetAttribute(k_scan, cudaFuncAttributeMaxDynamicSharedMemorySize, SM_TOTAL);
    smem_set = 1;
  }

  void *xn_p, *cfcx_p, *P0_p, *cfco_p, *zero_p, *bar_p;
  cudaGetSymbolAddress(&xn_p,   g_xn);
  cudaGetSymbolAddress(&cfcx_p, g_cfcx);
  cudaGetSymbolAddress(&P0_p,   g_P0);
  cudaGetSymbolAddress(&cfco_p, g_cfco);
  cudaGetSymbolAddress(&zero_p, g_zero);
  cudaGetSymbolAddress(&bar_p,  g_barA);

  cudaMemsetAsync(bar_p, 0, 16 * sizeof(unsigned), 0);

  k_initT<<<(U_ * B_) / 256, 256>>>(hid);

  k_pack<<<(NP4A + NP4H + 255) / 256, 256>>>(bbw, wff1, wff2, wta, wtb);

  k_ln<<<B_ * T_, 256>>>(x, nw, nb);

  // cfc_x = xn @ w_in + b_in
  k_gemm<<<dim3(D_ / 128, (B_ * T_) / 64), 256>>>(
      (const float*)xn_p, w_in, b_in, nullptr, (float*)cfcx_p,
      B_ * T_, D_, D_);

  // P0 = cfc_x @ W0[:1024,:]  (x-half of bb layer 0, no bias)
  k_gemm<<<dim3(BBU_ / 128, (B_ * T_) / 64), 256>>>(
      (const float*)cfcx_p, bbw, (const float*)zero_p, nullptr, (float*)P0_p,
      B_ * T_, BBU_, D_);

  k_transP0<<<dim3(BBU_ / 32, T_), 256>>>();

  float* hf = ((size_t)out_size >= (size_t)B_ * T_ * D_ + (size_t)B_ * U_)
                  ? out + (size_t)B_ * T_ * D_ : nullptr;
  k_scan<<<NBLK, NTHR, SM_TOTAL>>>(tsp, bbw, bbb, bff1, bff2, bta, btb, hf);

  // y = x + cfc_out @ w_out + b_out
  k_gemm<<<dim3(D_ / 128, (B_ * T_) / 64), 256>>>(
      (const float*)cfco_p, wout, bout, x, out,
      B_ * T_, U_, D_);
}

// round 15
// speedup vs baseline: 1.1071x; 1.1071x over previous
#include <cuda_runtime.h>
#include <cstddef>
#include <math.h>
#include <stdint.h>

#define B_ 32
#define T_ 512
#define D_ 1024
#define U_ 1024
#define BBU_ 2048
#define NBLK 128
#define NTHR 544            // 16 compute warps + 1 TMA producer warp
#define NCOMP 512
#define RING 4
#define NCHUNK (T_ * 20)

typedef unsigned long long ull;

// ---------------- persistent scratch (device globals; no runtime alloc) ----------------
__device__ float g_xn[B_*T_*D_];        // layernormed x
__device__ float g_cfcx[B_*T_*D_];      // xn @ w_in + b_in           [b][t][d]
__device__ float g_P0[B_*T_*BBU_];      // cfc_x @ W0[:1024]          [b*t][c]
__device__ float g_P0T[T_*BBU_*B_];     // transposed                 [t][c][b]
__device__ float g_cfco[B_*T_*U_];      // scan outputs               [b][t][u]
__device__ float g_h[U_*B_];            // hidden, pair layout [u/2][b][2]
__device__ float g_bb0[BBU_*B_];        // bb l0 out, pair layout [c/2][b][2]
__device__ float g_bb1[BBU_*B_];        // bb l1 out, pair layout
__device__ float g_pkA[NBLK*1024*16];   // packed W0h per-CTA slices (8MB)
__device__ float g_pkH[NBLK*2048*32];   // packed head weights per-CTA (32MB)
__device__ float g_zero[BBU_];          // zero bias
__device__ __align__(16) unsigned g_barA[16];  // hierarchical barrier counters

// ---------------- helpers ----------------
__device__ __forceinline__ unsigned sptr(const void* p){
  return (unsigned)__cvta_generic_to_shared(p);
}

// named barrier over the 512 compute threads (producer warp excluded)
__device__ __forceinline__ void barc(){
  asm volatile("bar.sync 1, 512;" ::: "memory");
}

// hierarchical grid barrier: 16 counters, 8 CTAs each; target = nbar*8 per counter
// (compute warps only)
__device__ __forceinline__ void grid_bar(int cta, unsigned target){
  barc();
  if (threadIdx.x == 0){
    __threadfence();                       // release our stage writes
    atomicAdd(&g_barA[cta & 15], 1u);
    while (true){
      bool ok = true;
      #pragma unroll
      for (int i = 0; i < 4; i++){
        uint4 v;
        asm volatile("ld.volatile.global.v4.u32 {%0,%1,%2,%3}, [%4];"
                     : "=r"(v.x), "=r"(v.y), "=r"(v.z), "=r"(v.w)
                     : "l"(g_barA + i * 4));
        ok &= (v.x >= target) & (v.y >= target) & (v.z >= target) & (v.w >= target);
      }
      if (ok) break;
      __nanosleep(16);
    }
    __threadfence();                       // acquire: gpu fence invalidates L1D
  }
  barc();
}

__device__ __forceinline__ ull fma2(ull x, ull y, ull z){
  ull d;
  asm("fma.rn.f32x2 %0, %1, %2, %3;" : "=l"(d) : "l"(x), "l"(y), "l"(z));
  return d;
}
__device__ __forceinline__ ull pack2(float a){
  unsigned au = __float_as_uint(a);
  ull p;
  asm("mov.b64 %0, {%1, %1};" : "=l"(p) : "r"(au));
  return p;
}
__device__ __forceinline__ void unpack2(ull v, float& lo, float& hi){
  unsigned l, h;
  asm("mov.b64 {%0, %1}, %2;" : "=r"(l), "=r"(h) : "l"(v));
  lo = __uint_as_float(l); hi = __uint_as_float(h);
}
#define LL(x) __double_as_longlong(x)

// mbarrier ops
__device__ __forceinline__ void mbar_init(unsigned mb, unsigned cnt){
  asm volatile("mbarrier.init.shared.b64 [%0], %1;" :: "r"(mb), "r"(cnt) : "memory");
}
__device__ __forceinline__ void mbar_arrive(unsigned mb){
  asm volatile("mbarrier.arrive.shared.b64 _, [%0];" :: "r"(mb) : "memory");
}
__device__ __forceinline__ void tma_issue(unsigned mb, unsigned dst, const float* src){
  asm volatile("mbarrier.arrive.expect_tx.shared.b64 _, [%0], %1;"
               :: "r"(mb), "r"(16384u) : "memory");
  asm volatile("cp.async.bulk.shared::cta.global.mbarrier::complete_tx::bytes "
               "[%0], [%1], %2, [%3];"
               :: "r"(dst), "l"(src), "r"(16384u), "r"(mb) : "memory");
}
__device__ __forceinline__ void mbar_wait(unsigned mb, unsigned ph){
  unsigned done;
  do {
    asm volatile(
      "{\n\t.reg .pred p;\n\t"
      "mbarrier.try_wait.parity.shared::cta.b64 p, [%1], %2, 0x989680;\n\t"
      "selp.b32 %0, 1, 0, p;\n\t}"
      : "=r"(done) : "r"(mb), "r"(ph) : "memory");
  } while (!done);
}

// 16KB chunks: per step 4 chunks of pkA (bb0-h) + 16 chunks of pkH (head)
__device__ __forceinline__ const float* chunk_src(int cta, int chunk){
  int p = chunk % 20;
  return (p < 4) ? g_pkA + (((size_t)cta) << 14) + ((size_t)p << 12)
                 : g_pkH + (((size_t)cta) << 16) + ((size_t)(p - 4) << 12);
}

// ---------------- LayerNorm ----------------
__global__ void k_ln(const float* __restrict__ x, const float* __restrict__ gw,
                     const float* __restrict__ gb){
  int row = blockIdx.x;
  int tid = threadIdx.x;
  const float4* xr = (const float4*)(x + (size_t)row * D_);
  float4 v = xr[tid];
  float s = v.x + v.y + v.z + v.w;
  float q = v.x*v.x + v.y*v.y + v.z*v.z + v.w*v.w;
  #pragma unroll
  for (int o = 16; o > 0; o >>= 1){
    s += __shfl_xor_sync(0xffffffffu, s, o);
    q += __shfl_xor_sync(0xffffffffu, q, o);
  }
  __shared__ float ss[8], sq[8];
  if ((tid & 31) == 0){ ss[tid >> 5] = s; sq[tid >> 5] = q; }
  __syncthreads();
  if (tid == 0){
    float a = 0.f, c = 0.f;
    #pragma unroll
    for (int i = 0; i < 8; i++){ a += ss[i]; c += sq[i]; }
    ss[0] = a; sq[0] = c;
  }
  __syncthreads();
  float mu  = ss[0] * (1.0f / D_);
  float var = sq[0] * (1.0f / D_) - mu * mu;
  float r   = rsqrtf(var + 1e-5f);
  float4 wv = ((const float4*)gw)[tid];
  float4 bv = ((const float4*)gb)[tid];
  float4 o;
  o.x = (v.x - mu) * r * wv.x + bv.x;
  o.y = (v.y - mu) * r * wv.y + bv.y;
  o.z = (v.z - mu) * r * wv.z + bv.z;
  o.w = (v.w - mu) * r * wv.w + bv.w;
  ((float4*)(g_xn + (size_t)row * D_))[tid] = o;
}

// ---------------- generic fp32 SGEMM: C = A[M,K]@W[K,N] + bias (+res) ----------------
__global__ void __launch_bounds__(256) k_gemm(
    const float* __restrict__ A, const float* __restrict__ W,
    const float* __restrict__ bias, const float* __restrict__ res,
    float* __restrict__ C, int M, int N, int K)
{
  __shared__ float As[16][64];
  __shared__ float Ws[16][64];
  int tid = threadIdx.x;
  int bn = blockIdx.x * 64, bm = blockIdx.y * 64;
  int tx = tid & 15, ty = tid >> 4;
  int lam = tid >> 2, lak = (tid & 3) * 4;
  int lwk = tid >> 4, lwn = (tid & 15) * 4;
  float acc[4][4] = {};
  for (int k0 = 0; k0 < K; k0 += 16){
    float4 av = *(const float4*)(A + (size_t)(bm + lam) * K + k0 + lak);
    As[lak+0][lam] = av.x; As[lak+1][lam] = av.y;
    As[lak+2][lam] = av.z; As[lak+3][lam] = av.w;
    *(float4*)&Ws[lwk][lwn] = *(const float4*)(W + (size_t)(k0 + lwk) * N + bn + lwn);
    __syncthreads();
    #pragma unroll
    for (int k = 0; k < 16; k++){
      float4 a4 = *(float4*)&As[k][ty * 4];
      float4 b4 = *(float4*)&Ws[k][tx * 4];
      acc[0][0] = fmaf(a4.x, b4.x, acc[0][0]); acc[0][1] = fmaf(a4.x, b4.y, acc[0][1]);
      acc[0][2] = fmaf(a4.x, b4.z, acc[0][2]); acc[0][3] = fmaf(a4.x, b4.w, acc[0][3]);
      acc[1][0] = fmaf(a4.y, b4.x, acc[1][0]); acc[1][1] = fmaf(a4.y, b4.y, acc[1][1]);
      acc[1][2] = fmaf(a4.y, b4.z, acc[1][2]); acc[1][3] = fmaf(a4.y, b4.w, acc[1][3]);
      acc[2][0] = fmaf(a4.z, b4.x, acc[2][0]); acc[2][1] = fmaf(a4.z, b4.y, acc[2][1]);
      acc[2][2] = fmaf(a4.z, b4.z, acc[2][2]); acc[2][3] = fmaf(a4.z, b4.w, acc[2][3]);
      acc[3][0] = fmaf(a4.w, b4.x, acc[3][0]); acc[3][1] = fmaf(a4.w, b4.y, acc[3][1]);
      acc[3][2] = fmaf(a4.w, b4.z, acc[3][2]); acc[3][3] = fmaf(a4.w, b4.w, acc[3][3]);
    }
    __syncthreads();
  }
  float4 bv = *(const float4*)(bias + bn + tx * 4);
  #pragma unroll
  for (int i = 0; i < 4; i++){
    size_t m = (size_t)bm + ty * 4 + i;
    float4 o = make_float4(acc[i][0] + bv.x, acc[i][1] + bv.y,
                           acc[i][2] + bv.z, acc[i][3] + bv.w);
    if (res){
      float4 rv = *(const float4*)(res + m * N + bn + tx * 4);
      o.x += rv.x; o.y += rv.y; o.z += rv.z; o.w += rv.w;
    }
    *(float4*)(C + m * N + bn + tx * 4) = o;
  }
}

// ---------------- transpose P0 [b][t][2048] -> [t][c][b] ----------------
__global__ void k_transP0(){
  __shared__ float tile[32][33];
  int c0 = blockIdx.x * 32, t = blockIdx.y;
  int lane = threadIdx.x & 31, r = threadIdx.x >> 5;
  #pragma unroll
  for (int i = 0; i < 4; i++){
    int b = r * 4 + i;
    tile[b][lane] = g_P0[((size_t)b * T_ + t) * BBU_ + c0 + lane];
  }
  __syncthreads();
  #pragma unroll
  for (int i = 0; i < 4; i++){
    int c = r * 4 + i;
    g_P0T[((size_t)t * BBU_ + c0 + c) * 32 + lane] = tile[lane][c];
  }
}

// ---------------- pack streamed weights + init h + zero barrier counters ----------------
#define NP4A (NBLK * 1024 * 4)
#define NP4H (NBLK * 2048 * 8)
__global__ void k_pack(const float* __restrict__ hid,
                       const float* __restrict__ W0,
                       const float* __restrict__ wff1, const float* __restrict__ wff2,
                       const float* __restrict__ wta,  const float* __restrict__ wtb){
  int q = blockIdx.x * 256 + threadIdx.x;
  if (q < 16) g_barA[q] = 0;              // reset grid-barrier counters each launch
  if (q < B_ * U_){                       // init hidden (pair layout)
    int u = q >> 5, b = q & 31;
    g_h[((u >> 1) << 6) + b * 2 + (u & 1)] = hid[(size_t)b * U_ + u];
  }
  if (q < NP4A){
    int cta = q >> 12, rem = q & 4095;
    int k = rem >> 2, c4 = (rem & 3) << 2;
    *(float4*)&g_pkA[(((size_t)cta << 10) + k) * 16 + c4] =
        *(const float4*)&W0[(size_t)(1024 + k) * BBU_ + cta * 16 + c4];
  } else if (q < NP4A + NP4H){
    int q2 = q - NP4A;
    int cta = q2 >> 14, rem = q2 & 16383;
    int k = rem >> 3, g8 = rem & 7;
    int m = g8 >> 1, h4 = (g8 & 1) << 2;
    const float* wm = (m == 0) ? wff1 : (m == 1) ? wff2 : (m == 2) ? wta : wtb;
    *(float4*)&g_pkH[(((size_t)cta << 11) + k) * 32 + m * 8 + h4] =
        *(const float4*)&wm[(size_t)k * U_ + cta * 8 + h4];
  }
}

// ---------------- persistent scan kernel ----------------
// SMEM: sW1 131072 | ring 4x16384 | red 33792 | mbars full[4]+empty[4]
#define SM_W1   0
#define SM_RING 131072
#define SM_RED  (131072 + RING * 16384)
#define SM_MBAR (SM_RED + 33792)
#define SM_TOTAL (SM_MBAR + 64)

__global__ void __launch_bounds__(NTHR, 1) k_scan(
    const float* __restrict__ tsp,
    const float* __restrict__ bbw,  const float* __restrict__ bbb,
    const float* __restrict__ bff1, const float* __restrict__ bff2,
    const float* __restrict__ bta,  const float* __restrict__ btb,
    float* __restrict__ hf)
{
  extern __shared__ char smem[];
  float* sW1   = (float*)(smem + SM_W1);
  float* ringf = (float*)(smem + SM_RING);
  float* red   = (float*)(smem + SM_RED);
  unsigned fullb[RING], emptyb[RING], ringu[RING];
  #pragma unroll
  for (int s = 0; s < RING; s++){
    fullb[s]  = sptr(smem + SM_MBAR + s * 8);
    emptyb[s] = sptr(smem + SM_MBAR + 32 + s * 8);
    ringu[s]  = sptr(smem + SM_RING + s * 16384);
  }

  int tid = threadIdx.x, cta = blockIdx.x;
  int lane = tid & 31, w = tid >> 5;    // warps 0..15 compute, warp 16 = TMA producer
  unsigned nbar = 0;
  const float* W1 = bbw + (size_t)BBU_ * BBU_;
  const float* b1 = bbb + BBU_;

  if (tid == 0){
    #pragma unroll
    for (int s = 0; s < RING; s++){ mbar_init(fullb[s], 1); mbar_init(emptyb[s], 16); }
  }
  // load persistent W1 slice: sW1[k][16] (all 17 warps help)
  for (int i = tid; i < 2048 * 4; i += NTHR){
    int k = i >> 2, c4 = (i & 3) << 2;
    *(float4*)&sW1[k * 16 + c4] = *(const float4*)&W1[(size_t)k * BBU_ + cta * 16 + c4];
  }
  __syncthreads();   // full-CTA sync (all 17 warps) — mbars + sW1 visible

  // ===================== TMA producer warp =====================
  if (w == 16){
    if (lane == 0){
      for (int j = 0; j < NCHUNK; j++){
        int slot = j & 3;
        if (j >= RING){
          unsigned epar = ((unsigned)(j - RING) >> 2) & 1u;
          mbar_wait(emptyb[slot], epar);
        }
        tma_issue(fullb[slot], ringu[slot], chunk_src(cta, j));
      }
    }
    return;   // producer warp exits; never touches named barrier 1
  }

  // ===================== compute warps (512 threads) =====================
  // per-thread P0T index (used in bb0 reduction): cc = cta*16 + (tid>>5), b2 = tid&31
  const float* p0_addr = g_P0T + ((size_t)(cta * 16 + (tid >> 5))) * 32 + (tid & 31);

  int it = 0;
  for (int t = 0; t < T_; t++){
    // prefetch P0T term for this step early (DRAM-resident; hide behind chunk loop)
    float p0v = p0_addr[(size_t)t * BBU_ * 32];

    // ======= bb layer 0: 16 cols/warp (acc[8]), 16-way k-split; h-half streamed =======
    {
      ull acc[8] = {0ull,0ull,0ull,0ull,0ull,0ull,0ull,0ull};
      #pragma unroll
      for (int c = 0; c < 4; c++){
        int slot = it & 3; unsigned par = (unsigned)(it >> 2) & 1u;
        mbar_wait(fullb[slot], par);
        const float* wb = ringf + slot * 4096 + (w * 16) * 16;   // 16 local k-rows x 16 cols
        const float* ap = g_h + (size_t)((c * 256 + w * 16) >> 1) * 64 + lane * 2;
        #pragma unroll
        for (int kk = 0; kk < 8; kk++){
          float2 av = *(const float2*)(ap + kk * 64);
          ull a0 = pack2(av.x), a1 = pack2(av.y);
          const double2* e = (const double2*)(wb + kk * 32);       // even k row
          const double2* o = (const double2*)(wb + kk * 32 + 16);  // odd k row
          #pragma unroll
          for (int j = 0; j < 4; j++){
            double2 we = e[j], wo = o[j];
            acc[2*j]   = fma2(a0, LL(we.x), acc[2*j]);
            acc[2*j+1] = fma2(a0, LL(we.y), acc[2*j+1]);
            acc[2*j]   = fma2(a1, LL(wo.x), acc[2*j]);
            acc[2*j+1] = fma2(a1, LL(wo.y), acc[2*j+1]);
          }
        }
        if (lane == 0) mbar_arrive(emptyb[slot]);
        it++;
      }
      #pragma unroll
      for (int i = 0; i < 8; i++){
        float lo, hi; unpack2(acc[i], lo, hi);
        red[(w * 16 + 2*i    ) * 33 + lane] = lo;
        red[(w * 16 + 2*i + 1) * 33 + lane] = hi;
      }
      barc();
      int b2 = tid & 31, cl = tid >> 5;
      float s = 0.f;
      #pragma unroll
      for (int k2 = 0; k2 < 16; k2++) s += red[(k2 * 16 + cl) * 33 + b2];
      int cc = cta * 16 + cl;
      s += p0v + bbb[cc];
      g_bb0[((size_t)(cc >> 1)) * 64 + b2 * 2 + (cc & 1)] = 1.7159f * tanhf(0.666f * s);
    }
    grid_bar(cta, ++nbar * 8);

    // ======= bb layer 1: 16 cols/warp, 16-way k-split; weights persistent in SMEM =======
    {
      ull acc[8] = {0ull,0ull,0ull,0ull,0ull,0ull,0ull,0ull};
      const float* wb = sW1 + (w * 128) * 16;
      const float* ap = g_bb0 + (size_t)((w * 128) >> 1) * 64 + lane * 2;
      #pragma unroll 8
      for (int kk = 0; kk < 64; kk++){
        float2 av = *(const float2*)(ap + kk * 64);
        ull a0 = pack2(av.x), a1 = pack2(av.y);
        const double2* e = (const double2*)(wb + kk * 32);
        const double2* o = (const double2*)(wb + kk * 32 + 16);
        #pragma unroll
        for (int j = 0; j < 4; j++){
          double2 we = e[j], wo = o[j];
          acc[2*j]   = fma2(a0, LL(we.x), acc[2*j]);
          acc[2*j+1] = fma2(a0, LL(we.y), acc[2*j+1]);
          acc[2*j]   = fma2(a1, LL(wo.x), acc[2*j]);
          acc[2*j+1] = fma2(a1, LL(wo.y), acc[2*j+1]);
        }
      }
      #pragma unroll
      for (int i = 0; i < 8; i++){
        float lo, hi; unpack2(acc[i], lo, hi);
        red[(w * 16 + 2*i    ) * 33 + lane] = lo;
        red[(w * 16 + 2*i + 1) * 33 + lane] = hi;
      }
      barc();
      int b2 = tid & 31, cl = tid >> 5;
      float s = 0.f;
      #pragma unroll
      for (int k2 = 0; k2 < 16; k2++) s += red[(k2 * 16 + cl) * 33 + b2];
      int cc = cta * 16 + cl;
      s += b1[cc];
      g_bb1[((size_t)(cc >> 1)) * 64 + b2 * 2 + (cc & 1)] = 1.7159f * tanhf(0.666f * s);
    }
    grid_bar(cta, ++nbar * 8);

    // ======= head: 16 cols/warp (2 col-groups x 8 k-split); weights streamed =======
    {
      ull acc[8] = {0ull,0ull,0ull,0ull,0ull,0ull,0ull,0ull};
      int g = w & 1, ks = w >> 1;
      for (int c = 0; c < 16; c++){
        int slot = it & 3; unsigned par = (unsigned)(it >> 2) & 1u;
        mbar_wait(fullb[slot], par);
        const float* wb = ringf + slot * 4096 + (ks * 16) * 32 + g * 16;
        const float* ap = g_bb1 + (size_t)((c * 128 + ks * 16) >> 1) * 64 + lane * 2;
        #pragma unroll
        for (int kk = 0; kk < 8; kk++){
          float2 av = *(const float2*)(ap + kk * 64);
          ull a0 = pack2(av.x), a1 = pack2(av.y);
          const double2* e = (const double2*)(wb + kk * 64);
          const double2* o = (const double2*)(wb + kk * 64 + 32);
          #pragma unroll
          for (int j = 0; j < 4; j++){
            double2 we = e[j], wo = o[j];
            acc[2*j]   = fma2(a0, LL(we.x), acc[2*j]);
            acc[2*j+1] = fma2(a0, LL(we.y), acc[2*j+1]);
            acc[2*j]   = fma2(a1, LL(wo.x), acc[2*j]);
            acc[2*j+1] = fma2(a1, LL(wo.y), acc[2*j+1]);
          }
        }
        if (lane == 0) mbar_arrive(emptyb[slot]);
        it++;
      }
      #pragma unroll
      for (int i = 0; i < 8; i++){
        float lo, hi; unpack2(acc[i], lo, hi);
        red[(ks * 32 + g * 16 + 2*i    ) * 33 + lane] = lo;
        red[(ks * 32 + g * 16 + 2*i + 1) * 33 + lane] = hi;
      }
      barc();
      if (tid < 256){
        int b2 = tid >> 3, uu = tid & 7;
        float s0 = 0.f, s1 = 0.f, s2 = 0.f, s3 = 0.f;
        #pragma unroll
        for (int k2 = 0; k2 < 8; k2++){
          s0 += red[(k2 * 32 +  0 + uu) * 33 + b2];
          s1 += red[(k2 * 32 +  8 + uu) * 33 + b2];
          s2 += red[(k2 * 32 + 16 + uu) * 33 + b2];
          s3 += red[(k2 * 32 + 24 + uu) * 33 + b2];
        }
        int u = cta * 8 + uu;
        float f1  = tanhf(s0 + bff1[u]);
        float f2  = tanhf(s1 + bff2[u]);
        float tav = s2 + bta[u], tbv = s3 + btb[u];
        float ts  = tsp[(size_t)b2 * T_ + t];
        float sig = 1.f / (1.f + expf(-(tav * ts + tbv)));
        float hn  = f1 * (1.f - sig) + sig * f2;
        g_h[((size_t)(u >> 1)) * 64 + b2 * 2 + (u & 1)] = hn;
        g_cfco[((size_t)b2 * T_ + t) * U_ + u] = hn;
      }
    }
    grid_bar(cta, ++nbar * 8);
  }

  if (hf){
    for (int i = cta * NCOMP + tid; i < B_ * U_; i += NBLK * NCOMP){
      int b = i >> 10, u = i & 1023;
      hf[i] = g_h[((size_t)(u >> 1)) * 64 + b * 2 + (u & 1)];
    }
  }
}

// ---------------- launch ----------------
extern "C" void kernel_launch(void* const* d_in, const int* in_sizes, int n_in,
                              void* d_out, int out_size){
  (void)in_sizes; (void)n_in;
  const float* x    = (const float*)d_in[0];
  const float* tsp  = (const float*)d_in[1];
  const float* hid  = (const float*)d_in[2];
  const float* nw   = (const float*)d_in[3];
  const float* nb   = (const float*)d_in[4];
  const float* w_in = (const float*)d_in[5];
  const float* b_in = (const float*)d_in[6];
  const float* bbw  = (const float*)d_in[7];
  const float* bbb  = (const float*)d_in[8];
  const float* wff1 = (const float*)d_in[9];
  const float* bff1 = (const float*)d_in[10];
  const float* wff2 = (const float*)d_in[11];
  const float* bff2 = (const float*)d_in[12];
  const float* wta  = (const float*)d_in[13];
  const float* bta  = (const float*)d_in[14];
  const float* wtb  = (const float*)d_in[15];
  const float* btb  = (const float*)d_in[16];
  const float* wout = (const float*)d_in[17];
  const float* bout = (const float*)d_in[18];
  float* out = (float*)d_out;

  static int smem_set = 0;
  if (!smem_set){
    cudaFuncSetAttribute(k_scan, cudaFuncAttributeMaxDynamicSharedMemorySize, SM_TOTAL);
    smem_set = 1;
  }

  void *xn_p, *cfcx_p, *P0_p, *cfco_p, *zero_p;
  cudaGetSymbolAddress(&xn_p,   g_xn);
  cudaGetSymbolAddress(&cfcx_p, g_cfcx);
  cudaGetSymbolAddress(&P0_p,   g_P0);
  cudaGetSymbolAddress(&cfco_p, g_cfco);
  cudaGetSymbolAddress(&zero_p, g_zero);

  // launch 0: pack weights + init h + zero barrier counters
  k_pack<<<(NP4A + NP4H + 255) / 256, 256>>>(hid, bbw, wff1, wff2, wta, wtb);

  // launch 1
  k_ln<<<B_ * T_, 256>>>(x, nw, nb);

  // launch 2: cfc_x = xn @ w_in + b_in
  k_gemm<<<dim3(D_ / 64, (B_ * T_) / 64), 256>>>(
      (const float*)xn_p, w_in, b_in, nullptr, (float*)cfcx_p,
      B_ * T_, D_, D_);

  // launch 3: P0 = cfc_x @ W0[:1024,:]  (x-half of bb layer 0, no bias)
  k_gemm<<<dim3(BBU_ / 64, (B_ * T_) / 64), 256>>>(
      (const float*)cfcx_p, bbw, (const float*)zero_p, nullptr, (float*)P0_p,
      B_ * T_, BBU_, D_);

  // launch 4
  k_transP0<<<dim3(BBU_ / 32, T_), 256>>>();

  // launch 5: the scan (ncu -s 5 -c 1 captures THIS)
  float* hf = ((size_t)out_size >= (size_t)B_ * T_ * D_ + (size_t)B_ * U_)
                  ? out + (size_t)B_ * T_ * D_ : nullptr;
  k_scan<<<NBLK, NTHR, SM_TOTAL>>>(tsp, bbw, bbb, bff1, bff2, bta, btb, hf);

  // launch 6: y = x + cfc_out @ w_out + b_out
  k_gemm<<<dim3(D_ / 64, (B_ * T_) / 64), 256>>>(
      (const float*)cfco_p, wout, bout, x, out,
      B_ * T_, U_, D_);
}